// round 1
// baseline (speedup 1.0000x reference)
#include <cuda_runtime.h>
#include <cuda_bf16.h>
#include <cstdint>
#include <cstddef>

#define NCTA   148
#define TSTEPS 2048

// ---------------- static device storage (allowed scratch) ----------------
__device__ __align__(16) __nv_bfloat16 g_W1t[(size_t)512  * 2560]; // [out][in] in=[h2(2048);x(512)]
__device__ __align__(16) __nv_bfloat16 g_J1t[(size_t)2048 * 3072];
__device__ __align__(16) __nv_bfloat16 g_K1t[(size_t)2048 * 3072];
__device__ __align__(16) __nv_bfloat16 g_J2t[(size_t)2048 * 4096];
__device__ __align__(16) __nv_bfloat16 g_K2t[(size_t)2048 * 4096];
__device__ __align__(16) __nv_bfloat16 g_W2t[(size_t)512  * 2048];

__device__ float g_a[512];
__device__ float g_out[512];
__device__ float g_h1[2][2048];
__device__ float g_h2[2][2048];
__device__ unsigned g_bar;

// ---------------- transpose + fp32->bf16 convert ----------------
// src: [fan_in, fan_out] fp32 row-major  ->  dst: [fan_out][fan_in] bf16
__global__ void transpose_convert(const float* __restrict__ src, int which, int fi, int fo)
{
    __shared__ float tile[32][33];
    __nv_bfloat16* dst =
        which == 0 ? g_W1t : which == 1 ? g_J1t : which == 2 ? g_K1t :
        which == 3 ? g_J2t : which == 4 ? g_K2t : g_W2t;
    int o0 = blockIdx.x * 32, i0 = blockIdx.y * 32;
    for (int r = threadIdx.y; r < 32; r += 8)
        tile[r][threadIdx.x] = src[(size_t)(i0 + r) * fo + o0 + threadIdx.x];
    __syncthreads();
    for (int r = threadIdx.y; r < 32; r += 8)
        dst[(size_t)(o0 + r) * fi + i0 + threadIdx.x] = __float2bfloat16(tile[threadIdx.x][r]);
}

__global__ void init_state()
{
    int i = blockIdx.x * blockDim.x + threadIdx.x;
    if (i == 0) g_bar = 0u;
    if (i < 512) g_out[i] = 0.f;
    if (i < 2048) { g_h1[0][i] = 0.f; g_h2[0][i] = 0.f; }
}

// ---------------- helpers ----------------
__device__ __forceinline__ float bflo(unsigned w) { return __uint_as_float(w << 16); }
__device__ __forceinline__ float bfhi(unsigned w) { return __uint_as_float(w & 0xffff0000u); }

// 16B-granular XOR swizzle: kills 2-way LDS.128 bank conflicts of the lane*32B pattern
__device__ __forceinline__ int swz(int i) { return i ^ (((i >> 5) & 1) << 2); }

__device__ __forceinline__ float wredsum(float a)
{
#pragma unroll
    for (int o = 16; o > 0; o >>= 1) a += __shfl_xor_sync(0xffffffffu, a, o);
    return a;
}

// dual-row dot: J-row and K-row share the activation reads
template <int NIT>
__device__ __forceinline__ float2 dotrow2(const __nv_bfloat16* __restrict__ wj,
                                          const __nv_bfloat16* __restrict__ wk,
                                          const float* __restrict__ v, int lane)
{
    const uint4* wpj = (const uint4*)wj;
    const uint4* wpk = (const uint4*)wk;
    float aj0 = 0.f, aj1 = 0.f, ak0 = 0.f, ak1 = 0.f;
#pragma unroll 4
    for (int it = 0; it < NIT; it++) {
        int base = it * 256 + lane * 8;
        float4 a = *(const float4*)(v + swz(base));
        float4 b = *(const float4*)(v + swz(base + 4));
        uint4 uj = wpj[it * 32 + lane];
        uint4 uk = wpk[it * 32 + lane];
        aj0 = fmaf(bflo(uj.x), a.x, aj0); aj1 = fmaf(bfhi(uj.x), a.y, aj1);
        aj0 = fmaf(bflo(uj.y), a.z, aj0); aj1 = fmaf(bfhi(uj.y), a.w, aj1);
        aj0 = fmaf(bflo(uj.z), b.x, aj0); aj1 = fmaf(bfhi(uj.z), b.y, aj1);
        aj0 = fmaf(bflo(uj.w), b.z, aj0); aj1 = fmaf(bfhi(uj.w), b.w, aj1);
        ak0 = fmaf(bflo(uk.x), a.x, ak0); ak1 = fmaf(bfhi(uk.x), a.y, ak1);
        ak0 = fmaf(bflo(uk.y), a.z, ak0); ak1 = fmaf(bfhi(uk.y), a.w, ak1);
        ak0 = fmaf(bflo(uk.z), b.x, ak0); ak1 = fmaf(bfhi(uk.z), b.y, ak1);
        ak0 = fmaf(bflo(uk.w), b.z, ak0); ak1 = fmaf(bfhi(uk.w), b.w, ak1);
    }
    return make_float2(aj0 + aj1, ak0 + ak1);
}

template <int NIT>
__device__ __forceinline__ float dotrow(const __nv_bfloat16* __restrict__ w,
                                        const float* __restrict__ v, int lane)
{
    const uint4* wp = (const uint4*)w;
    float a0 = 0.f, a1 = 0.f;
#pragma unroll 4
    for (int it = 0; it < NIT; it++) {
        int base = it * 256 + lane * 8;
        float4 a = *(const float4*)(v + swz(base));
        float4 b = *(const float4*)(v + swz(base + 4));
        uint4 u = wp[it * 32 + lane];
        a0 = fmaf(bflo(u.x), a.x, a0); a1 = fmaf(bfhi(u.x), a.y, a1);
        a0 = fmaf(bflo(u.y), a.z, a0); a1 = fmaf(bfhi(u.y), a.w, a1);
        a0 = fmaf(bflo(u.z), b.x, a0); a1 = fmaf(bfhi(u.z), b.y, a1);
        a0 = fmaf(bflo(u.w), b.z, a0); a1 = fmaf(bfhi(u.w), b.w, a1);
    }
    return a0 + a1;
}

__device__ __forceinline__ float sigm(float z) { return 1.f / (1.f + __expf(-z)); }

// monotonic-counter grid barrier (all CTAs resident: grid=148 <= 152 SMs)
__device__ __forceinline__ void gsync(unsigned& target)
{
    __syncthreads();
    if (threadIdx.x == 0) {
        __threadfence();
        atomicAdd(&g_bar, 1u);
        target += NCTA;
        unsigned v;
        do {
            asm volatile("ld.acquire.gpu.u32 %0, [%1];" : "=r"(v) : "l"(&g_bar) : "memory");
        } while (v < target);
    }
    __syncthreads();
}

// ---------------- persistent RNN kernel ----------------
__global__ __launch_bounds__(1024, 1) void rnn_kernel(
    const float* __restrict__ X,
    const float* __restrict__ b1,  const float* __restrict__ J1b, const float* __restrict__ K1b,
    const float* __restrict__ J2b, const float* __restrict__ K2b, const float* __restrict__ b2,
    float* __restrict__ Y)
{
    __shared__ __align__(16) float sv[4096];
    const int tid  = threadIdx.x;
    const int lane = tid & 31;
    const int wid  = tid >> 5;
    const int cta  = blockIdx.x;
    const int r    = wid * NCTA + cta;   // global work index for this warp
    unsigned target = 0;

    // ---- pre-phase: a_0 = b1 + W1[x-part]^T x_0   (h2 = 0)
    for (int i = tid; i < 512; i += 1024) sv[swz(i)] = X[i];
    __syncthreads();
    if (r < 512) {
        float acc = dotrow<2>(&g_W1t[(size_t)r * 2560 + 2048], sv, lane);
        acc = wredsum(acc);
        if (lane == 0) g_a[r] = acc + b1[r];
    }
    gsync(target);

    for (int t = 0; t < TSTEPS; t++) {
        const int p = t & 1;

        // ---- phase 1: c1=[a; out; h1_old], compute h1_new
        for (int i = tid; i < 512; i += 1024) {
            sv[swz(i)]       = __ldcg(&g_a[i]);
            sv[swz(512 + i)] = __ldcg(&g_out[i]);
        }
        for (int i = tid; i < 2048; i += 1024) sv[swz(1024 + i)] = __ldcg(&g_h1[p][i]);
        __syncthreads();
        if (r < 2048) {
            float2 zz = dotrow2<12>(&g_J1t[(size_t)r * 3072], &g_K1t[(size_t)r * 3072], sv, lane);
            float zj = wredsum(zz.x);
            float zk = wredsum(zz.y);
            if (lane == 0) {
                float j = sigm(zj + J1b[r]);
                float k = sigm(zk + K1b[r]);
                float h = __ldcg(&g_h1[p][r]);
                g_h1[p ^ 1][r] = fmaf(j, 1.f - h, (1.f - k) * h);
            }
        }
        gsync(target);

        // ---- phase 2: c2=[h1_new; h2_old], compute h2_new
        for (int i = tid; i < 2048; i += 1024) {
            sv[swz(i)]        = __ldcg(&g_h1[p ^ 1][i]);
            sv[swz(2048 + i)] = __ldcg(&g_h2[p][i]);
        }
        __syncthreads();
        if (r < 2048) {
            float2 zz = dotrow2<16>(&g_J2t[(size_t)r * 4096], &g_K2t[(size_t)r * 4096], sv, lane);
            float zj = wredsum(zz.x);
            float zk = wredsum(zz.y);
            if (lane == 0) {
                float j = sigm(zj + J2b[r]);
                float k = sigm(zk + K2b[r]);
                float h = __ldcg(&g_h2[p][r]);
                g_h2[p ^ 1][r] = fmaf(j, 1.f - h, (1.f - k) * h);
            }
        }
        gsync(target);

        // ---- phase 3: out_t = sigmoid(W2^T h2_new + b2); a_{t+1} = W1^T [h2_new; x_{t+1}] + b1
        const bool hasNext = (t + 1) < TSTEPS;
        for (int i = tid; i < 2048; i += 1024) sv[swz(i)] = __ldcg(&g_h2[p ^ 1][i]);
        if (hasNext)
            for (int i = tid; i < 512; i += 1024) sv[swz(2048 + i)] = X[(size_t)(t + 1) * 512 + i];
        __syncthreads();
        if (r < 512) {
            float acc = dotrow<8>(&g_W2t[(size_t)r * 2048], sv, lane);
            acc = wredsum(acc);
            if (lane == 0) {
                float s = sigm(acc + b2[r]);
                g_out[r] = s;
                Y[(size_t)t * 512 + r] = s;
            }
        } else if (r < 1024 && hasNext) {
            const int i = r - 512;
            float acc = dotrow<10>(&g_W1t[(size_t)i * 2560], sv, lane);
            acc = wredsum(acc);
            if (lane == 0) g_a[i] = acc + b1[i];
        }
        gsync(target);
    }
}

// ---------------- launch ----------------
extern "C" void kernel_launch(void* const* d_in, const int* in_sizes, int n_in,
                              void* d_out, int out_size)
{
    (void)in_sizes; (void)n_in; (void)out_size;
    const float* X   = (const float*)d_in[0];
    const float* W1  = (const float*)d_in[1];
    const float* b1  = (const float*)d_in[2];
    const float* J1W = (const float*)d_in[3];
    const float* J1b = (const float*)d_in[4];
    const float* K1W = (const float*)d_in[5];
    const float* K1b = (const float*)d_in[6];
    const float* J2W = (const float*)d_in[7];
    const float* J2b = (const float*)d_in[8];
    const float* K2W = (const float*)d_in[9];
    const float* K2b = (const float*)d_in[10];
    const float* W2  = (const float*)d_in[11];
    const float* b2  = (const float*)d_in[12];
    float* Y = (float*)d_out;

    dim3 tb(32, 8);
    transpose_convert<<<dim3(512 / 32, 2560 / 32), tb>>>(W1, 0, 2560, 512);
    transpose_convert<<<dim3(2048 / 32, 3072 / 32), tb>>>(J1W, 1, 3072, 2048);
    transpose_convert<<<dim3(2048 / 32, 3072 / 32), tb>>>(K1W, 2, 3072, 2048);
    transpose_convert<<<dim3(2048 / 32, 4096 / 32), tb>>>(J2W, 3, 4096, 2048);
    transpose_convert<<<dim3(2048 / 32, 4096 / 32), tb>>>(K2W, 4, 4096, 2048);
    transpose_convert<<<dim3(512 / 32, 2048 / 32), tb>>>(W2, 5, 2048, 512);
    init_state<<<2, 1024>>>();
    rnn_kernel<<<NCTA, 1024>>>(X, b1, J1b, K1b, J2b, K2b, b2, Y);
}